// round 14
// baseline (speedup 1.0000x reference)
#include <cuda_runtime.h>
#include <cuda_fp16.h>
#include <cstdint>
#include <cstddef>

#define EDIM 1024
#define NHEAD 16
#define HDIM 64
#define FFDIM 4096
#define BATCH 4
#define SEQ 2048
#define NTOK (BATCH*SEQ)   // 8192

// ------------------- scratch (device globals; no allocations) -------------------
__device__ __half   g_qln_h[(size_t)NTOK*EDIM];
__device__ float    g_qln  [(size_t)NTOK*EDIM];   // raw fp32 residual
__device__ __half   g_vln_h[(size_t)NTOK*EDIM];
__device__ __half   g_kln_h[(size_t)NTOK*EDIM];
__device__ __half   g_Q [(size_t)NTOK*EDIM];
__device__ __half   g_K [(size_t)NTOK*EDIM];
__device__ __half   g_V [(size_t)NTOK*EDIM];
__device__ uint32_t g_Vp[(size_t)NTOK/2*EDIM];    // token-pair packed V
__device__ __half   g_att[(size_t)NTOK*EDIM];
__device__ float    g_x [(size_t)NTOK*EDIM];
__device__ __half   g_hh[(size_t)NTOK*EDIM];
__device__ __half   g_ff[(size_t)NTOK*FFDIM];
__device__ float    g_maskf[(size_t)BATCH*SEQ];
// weights packed TRANSPOSED: [N][K/2] half2-k-pair words
__device__ uint32_t g_Wq[(size_t)EDIM*EDIM/2];
__device__ uint32_t g_Wk[(size_t)EDIM*EDIM/2];
__device__ uint32_t g_Wv[(size_t)EDIM*EDIM/2];
__device__ uint32_t g_Wo[(size_t)EDIM*EDIM/2];
__device__ uint32_t g_W1[(size_t)FFDIM*EDIM/2];   // [4096][512]
__device__ uint32_t g_W2[(size_t)EDIM*FFDIM/2];   // [1024][2048]

// ------------------- helpers -------------------
__device__ __forceinline__ uint32_t pack2(float lo, float hi) {
    __half2 h = __floats2half2_rn(lo, hi);
    return *reinterpret_cast<uint32_t*>(&h);
}

__device__ __forceinline__ void mma16(float* c, const uint32_t* a, const uint32_t* b) {
    asm volatile(
        "mma.sync.aligned.m16n8k16.row.col.f32.f16.f16.f32 "
        "{%0,%1,%2,%3},{%4,%5,%6,%7},{%8,%9},{%0,%1,%2,%3};\n"
        : "+f"(c[0]), "+f"(c[1]), "+f"(c[2]), "+f"(c[3])
        : "r"(a[0]), "r"(a[1]), "r"(a[2]), "r"(a[3]), "r"(b[0]), "r"(b[1]));
}

#define LDSM4(R0,R1,R2,R3,ADDR) \
    asm volatile("ldmatrix.sync.aligned.m8n8.x4.shared.b16 {%0,%1,%2,%3}, [%4];\n" \
        : "=r"(R0), "=r"(R1), "=r"(R2), "=r"(R3) : "r"(ADDR))

__device__ __forceinline__ float gelu_exact(float v) {
    return 0.5f * v * (1.0f + erff(v * 0.70710678118654752f));
}

#define CP16(dst_sm, src_g) \
    asm volatile("cp.async.cg.shared.global [%0], [%1], 16;\n" :: \
        "r"((uint32_t)__cvta_generic_to_shared(dst_sm)), "l"(src_g))
#define CP_COMMIT() asm volatile("cp.async.commit_group;\n")
#define CP_WAIT1()  asm volatile("cp.async.wait_group 1;\n")
#define CP_WAIT0()  asm volatile("cp.async.wait_group 0;\n")

// ------------------- mask -> float addend -------------------
__global__ __launch_bounds__(256) void maskf_kernel(
    const int* __restrict__ mask, float* __restrict__ mf)
{
    int i = blockIdx.x * 256 + threadIdx.x;
    mf[i] = (mask[i] == 0) ? -1e20f : 0.0f;
}

// ---- weight pack+transpose: fp32 [K][N] -> words [N][K/2] (k-pair minor) ----
__global__ __launch_bounds__(256) void wpackT_kernel(
    const float* __restrict__ W, uint32_t* __restrict__ Wp, int K, int N)
{
    __shared__ float sm[256][33];
    int n0 = blockIdx.x * 32, k0 = blockIdx.y * 256;
    int tid = threadIdx.x;
    #pragma unroll
    for (int i = 0; i < 8; i++) {
        int idx = tid + i * 256;
        int r = idx >> 3, c4 = (idx & 7) * 4;
        float4 v = *reinterpret_cast<const float4*>(W + (size_t)(k0 + r) * N + n0 + c4);
        sm[r][c4] = v.x; sm[r][c4+1] = v.y; sm[r][c4+2] = v.z; sm[r][c4+3] = v.w;
    }
    __syncthreads();
    int Kw = K >> 1;
    #pragma unroll
    for (int i = 0; i < 4; i++) {
        int idx = tid + i * 256;
        int wc = (idx & 7) * 4;
        int n  = (idx >> 3) & 31;
        int kb = idx >> 8;
        int w  = kb * 32 + wc;
        uint4 o;
        o.x = pack2(sm[2*w  ][n], sm[2*w+1][n]);
        o.y = pack2(sm[2*w+2][n], sm[2*w+3][n]);
        o.z = pack2(sm[2*w+4][n], sm[2*w+5][n]);
        o.w = pack2(sm[2*w+6][n], sm[2*w+7][n]);
        *reinterpret_cast<uint4*>(Wp + (size_t)(n0 + n) * Kw + (k0 >> 1) + w) = o;
    }
}

// ------------------- V pack: half [NTOK][E] -> token-pair words [NTOK/2][E] ----
__global__ __launch_bounds__(256) void vpack_kernel(
    const uint32_t* __restrict__ Vh, uint32_t* __restrict__ Vp)
{
    int gid = blockIdx.x * 256 + threadIdx.x;
    int pg = gid >> 8;
    int n = (gid & 255) * 4;
    uint2 a = *reinterpret_cast<const uint2*>(Vh + (size_t)(2 * pg) * 512 + (n >> 1));
    uint2 b = *reinterpret_cast<const uint2*>(Vh + (size_t)(2 * pg + 1) * 512 + (n >> 1));
    uint4 o;
    o.x = (a.x & 0xFFFFu) | (b.x << 16);
    o.y = (a.x >> 16)     | (b.x & 0xFFFF0000u);
    o.z = (a.y & 0xFFFFu) | (b.y << 16);
    o.w = (a.y >> 16)     | (b.y & 0xFFFF0000u);
    *reinterpret_cast<uint4*>(Vp + (size_t)pg * 1024 + n) = o;
}

// ------------------- LayerNorm: warp-per-row -------------------
__global__ __launch_bounds__(256) void ln_kernel(
    const float* __restrict__ in, uint32_t* __restrict__ outh, float* __restrict__ out2,
    const float* __restrict__ gw, const float* __restrict__ gb)
{
    int warp = threadIdx.x >> 5, lane = threadIdx.x & 31;
    int row = blockIdx.x * 8 + warp;
    const float4* inr = reinterpret_cast<const float4*>(in + (size_t)row * EDIM);

    float4 v[8];
    float s = 0.0f, sq = 0.0f;
    #pragma unroll
    for (int i = 0; i < 8; i++) {
        v[i] = inr[lane + 32 * i];
        s  += v[i].x + v[i].y + v[i].z + v[i].w;
        sq += v[i].x*v[i].x + v[i].y*v[i].y + v[i].z*v[i].z + v[i].w*v[i].w;
    }
    #pragma unroll
    for (int o = 16; o > 0; o >>= 1) {
        s  += __shfl_xor_sync(0xffffffffu, s, o);
        sq += __shfl_xor_sync(0xffffffffu, sq, o);
    }
    float mean = s * (1.0f / EDIM);
    float var  = sq * (1.0f / EDIM) - mean * mean;
    float rstd = rsqrtf(var + 1e-5f);

    const float4* gw4 = reinterpret_cast<const float4*>(gw);
    const float4* gb4 = reinterpret_cast<const float4*>(gb);
    #pragma unroll
    for (int i = 0; i < 8; i++) {
        float4 gg = gw4[lane + 32 * i];
        float4 bb = gb4[lane + 32 * i];
        float4 o4;
        o4.x = (v[i].x - mean) * rstd * gg.x + bb.x;
        o4.y = (v[i].y - mean) * rstd * gg.y + bb.y;
        o4.z = (v[i].z - mean) * rstd * gg.z + bb.z;
        o4.w = (v[i].w - mean) * rstd * gg.w + bb.w;
        if (out2)
            reinterpret_cast<float4*>(out2 + (size_t)row * EDIM)[lane + 32 * i] = o4;
        uint2 w2;
        w2.x = pack2(o4.x, o4.y);
        w2.y = pack2(o4.z, o4.w);
        reinterpret_cast<uint2*>(outh + (size_t)row * 512)[lane + 32 * i] = w2;
    }
}

// ------------------- flash attention fp16 + ldmatrix Q/K ---------------------
#define FLASH_SMEM_WORDS 13824

__global__ __launch_bounds__(256, 2) void flash_kernel(
    const __half* __restrict__ Qg, const __half* __restrict__ Kg,
    const uint32_t* __restrict__ Vp, const float* __restrict__ maskf,
    uint32_t* __restrict__ Og)
{
    extern __shared__ uint32_t smu[];
    uint32_t* Qs = smu;
    uint32_t* Ks = smu + 4608;
    uint32_t* Vs = smu + 9216;
    uint32_t smbase = (uint32_t)__cvta_generic_to_shared(smu);

    int qt = blockIdx.x, h = blockIdx.y, b = blockIdx.z;
    int tokbase = b * SEQ + qt * 128;
    const uint32_t* Qw  = (const uint32_t*)Qg + (size_t)tokbase * 512 + h * 32;
    const __half*   Kb0 = Kg + (size_t)b * SEQ * EDIM + h * HDIM;
    const uint32_t* Vp0 = Vp + (size_t)(b * SEQ / 2) * EDIM + h * HDIM;
    const float*    mfb = maskf + (size_t)b * SEQ;

    int tid = threadIdx.x, w = tid >> 5, lane = tid & 31;
    int g = lane >> 2, t4 = lane & 3;
    int r0 = w * 16 + g;

    uint32_t ml = lane >> 3, rl = lane & 7;
    uint32_t qoff = (w * 16 + (ml & 1) * 8 + rl) * 36 + (ml >> 1) * 4;
    uint32_t koff = ((ml >> 1) * 8 + rl) * 36 + (ml & 1) * 4;

    __half2 sc = __float2half2_rn(0.125f);
    #pragma unroll
    for (int it = 0; it < 8; it++) {
        int idx = tid + it * 256;
        int r = idx >> 4, c = (idx & 15) * 2;
        uint2 v = *reinterpret_cast<const uint2*>(Qw + (size_t)r * 512 + c);
        __half2 h0 = __hmul2(*reinterpret_cast<__half2*>(&v.x), sc);
        __half2 h1 = __hmul2(*reinterpret_cast<__half2*>(&v.y), sc);
        uint2 o;
        o.x = *reinterpret_cast<uint32_t*>(&h0);
        o.y = *reinterpret_cast<uint32_t*>(&h1);
        *reinterpret_cast<uint2*>(&Qs[r * 36 + c]) = o;
    }

    auto issue_kv = [&](int j, int buf) {
        const __half* Kc = Kb0 + (size_t)j * 64 * EDIM;
        const uint32_t* Vc = Vp0 + (size_t)(j * 32) * EDIM;
        uint32_t* Kd = Ks + buf * 2304;
        uint32_t* Vd = Vs + buf * 2304;
        #pragma unroll
        for (int it = 0; it < 2; it++) {
            int idx = tid + it * 256;
            int r = idx >> 3, c = idx & 7;
            CP16(&Kd[r * 36 + c * 4], Kc + (size_t)r * EDIM + c * 8);
        }
        #pragma unroll
        for (int it = 0; it < 2; it++) {
            int idx = tid + it * 256;
            int p = idx >> 4, c = idx & 15;
            CP16(&Vd[p * 72 + c * 4], Vc + (size_t)p * EDIM + c * 4);
        }
    };

    issue_kv(0, 0);
    CP_COMMIT();

    float m0 = -1e30f, m1 = -1e30f, l0 = 0.0f, l1 = 0.0f;
    float oacc[8][4];
    #pragma unroll
    for (int nf = 0; nf < 8; nf++)
        #pragma unroll
        for (int i = 0; i < 4; i++) oacc[nf][i] = 0.0f;

    const int NCH = SEQ / 64;
    for (int j = 0; j < NCH; j++) {
        int buf = j & 1;
        if (j + 1 < NCH) { issue_kv(j + 1, buf ^ 1); CP_COMMIT(); CP_WAIT1(); }
        else             { CP_WAIT0(); }
        __syncthreads();

        const uint32_t* Vb = Vs + buf * 2304;
        uint32_t Qb = smbase + qoff * 4;
        uint32_t Kb = smbase + (4608 + buf * 2304 + koff) * 4;

        float sacc[8][4];
        #pragma unroll
        for (int nf = 0; nf < 8; nf++)
            #pragma unroll
            for (int i = 0; i < 4; i++) sacc[nf][i] = 0.0f;

        #pragma unroll
        for (int s = 0; s < 4; s++) {
            uint32_t afr[4];
            LDSM4(afr[0], afr[1], afr[2], afr[3], Qb + 8 * s * 4);
            uint32_t bfr[8][2];
            #pragma unroll
            for (int nf2 = 0; nf2 < 4; nf2++) {
                LDSM4(bfr[2*nf2][0], bfr[2*nf2][1], bfr[2*nf2+1][0], bfr[2*nf2+1][1],
                      Kb + (nf2 * 576 + 8 * s) * 4);
            }
            #pragma unroll
            for (int nf = 0; nf < 8; nf++)
                mma16(sacc[nf], afr, bfr[nf]);
        }

        const float2* mf2 = (const float2*)(mfb + j * 64);
        float mx0 = -1e30f, mx1 = -1e30f;
        #pragma unroll
        for (int nf = 0; nf < 8; nf++) {
            float2 md = mf2[nf * 4 + t4];
            sacc[nf][0] += md.x; sacc[nf][1] += md.y;
            sacc[nf][2] += md.x; sacc[nf][3] += md.y;
            mx0 = fmaxf(mx0, fmaxf(sacc[nf][0], sacc[nf][1]));
            mx1 = fmaxf(mx1, fmaxf(sacc[nf][2], sacc[nf][3]));
        }
        mx0 = fmaxf(mx0, __shfl_xor_sync(0xffffffffu, mx0, 1));
        mx0 = fmaxf(mx0, __shfl_xor_sync(0xffffffffu, mx0, 2));
        mx1 = fmaxf(mx1, __shfl_xor_sync(0xffffffffu, mx1, 1));
        mx1 = fmaxf(mx1, __shfl_xor_sync(0xffffffffu, mx1, 2));
        float mn0 = fmaxf(m0, mx0), mn1 = fmaxf(m1, mx1);
        float c0 = __expf(m0 - mn0), c1 = __expf(m1 - mn1);
        float s0 = 0.0f, s1 = 0.0f;
        uint32_t ppk0[8], ppk1[8];
        #pragma unroll
        for (int nf = 0; nf < 8; nf++) {
            float p00 = __expf(sacc[nf][0] - mn0);
            float p01 = __expf(sacc[nf][1] - mn0);
            float p10 = __expf(sacc[nf][2] - mn1);
            float p11 = __expf(sacc[nf][3] - mn1);
            s0 += p00 + p01; s1 += p10 + p11;
            ppk0[nf] = pack2(p00, p01);
            ppk1[nf] = pack2(p10, p11);
        }
        s0 += __shfl_xor_sync(0xffffffffu, s0, 1);
        s0 += __shfl_xor_sync(0xffffffffu, s0, 2);
        s1 += __shfl_xor_sync(0xffffffffu, s1, 1);
        s1 += __shfl_xor_sync(0xffffffffu, s1, 2);
        l0 = l0 * c0 + s0; l1 = l1 * c1 + s1;
        m0 = mn0; m1 = mn1;

        #pragma unroll
        for (int nf = 0; nf < 8; nf++) {
            oacc[nf][0] *= c0; oacc[nf][1] *= c0;
            oacc[nf][2] *= c1; oacc[nf][3] *= c1;
        }
        #pragma unroll
        for (int s = 0; s < 4; s++) {
            uint32_t afr[4];
            afr[0] = ppk0[2 * s];
            afr[1] = ppk1[2 * s];
            afr[2] = ppk0[2 * s + 1];
            afr[3] = ppk1[2 * s + 1];
            uint32_t bfr[8][2];
            #pragma unroll
            for (int nf = 0; nf < 8; nf++) {
                int n = nf * 8 + g;
                bfr[nf][0] = Vb[(8 * s + t4) * 72 + n];
                bfr[nf][1] = Vb[(8 * s + 4 + t4) * 72 + n];
            }
            #pragma unroll
            for (int nf = 0; nf < 8; nf++)
                mma16(oacc[nf], afr, bfr[nf]);
        }
        __syncthreads();
    }

    float inv0 = 1.0f / l0, inv1 = 1.0f / l1;
    uint32_t* Ob = Og + (size_t)tokbase * 512 + h * 32;
    #pragma unroll
    for (int nf = 0; nf < 8; nf++) {
        int cw = nf * 4 + t4;
        Ob[(size_t)r0 * 512 + cw]       = pack2(oacc[nf][0] * inv0, oacc[nf][1] * inv0);
        Ob[(size_t)(r0 + 8) * 512 + cw] = pack2(oacc[nf][2] * inv1, oacc[nf][3] * inv1);
    }
}

// ---- fp16 NN GEMM, ldmatrix both operands: CTA 256x128, warp 64x32, BK=64 ----
// 512 threads, occ 1 (16 warps/SM = 4/SMSP). A: half [M][K]; Bp: [N][K/2] words.
// smem: As 3 x 256x36, Bs 3 x 128x36 (n-major).
#define GEMM_SMEM_WORDS (3*9216 + 3*4608)

template<int EPI, int OUTH>
__global__ __launch_bounds__(512, 1) void gemm_h(
    const __half* __restrict__ A, const uint32_t* __restrict__ Bp, void* __restrict__ Cv,
    int K, int N, const float* __restrict__ bias, const float* __restrict__ res)
{
    extern __shared__ uint32_t smu[];
    uint32_t* As = smu;              // 3 x 256 x 36
    uint32_t* Bs = smu + 3 * 9216;   // 3 x 128 x 36 (rows = n)
    uint32_t smbase = (uint32_t)__cvta_generic_to_shared(smu);

    int m0 = blockIdx.y * 256, n0 = blockIdx.x * 128;
    int tid = threadIdx.x, warp = tid >> 5, lane = tid & 31;
    int wm = (warp >> 2) * 64, wn = (warp & 3) * 32;   // 4 m-bands x 4 n-bands
    int g = lane >> 2, t4 = lane & 3;

    // ldmatrix per-lane offsets (words within stage)
    uint32_t ml = lane >> 3, rl = lane & 7;
    uint32_t aoff = (wm + (ml & 1) * 8 + rl) * 36 + (ml >> 1) * 4;
    uint32_t boff = (wn + (ml >> 1) * 8 + rl) * 36 + (ml & 1) * 4;

    const int T = K >> 6;
    const int Kw = K >> 1;

    auto issue = [&](int t) {
        int s = t % 3;
        int k0 = t << 6, p0 = t << 5;
        uint32_t* Ad = As + s * 9216;
        uint32_t* Bd = Bs + s * 4608;
        #pragma unroll
        for (int it = 0; it < 4; it++) {
            int idx = tid + it * 512;
            int r = idx >> 3, c = idx & 7;
            CP16(&Ad[r * 36 + c * 4], A + (size_t)(m0 + r) * K + k0 + c * 8);
        }
        #pragma unroll
        for (int it = 0; it < 2; it++) {
            int idx = tid + it * 512;
            int r = idx >> 3, c = idx & 7;
            CP16(&Bd[r * 36 + c * 4], Bp + (size_t)(n0 + r) * Kw + p0 + c * 4);
        }
    };

    float acc[4][4][4];
    #pragma unroll
    for (int a = 0; a < 4; a++)
        #pragma unroll
        for (int c = 0; c < 4; c++)
            #pragma unroll
            for (int i = 0; i < 4; i++) acc[a][c][i] = 0.0f;

    issue(0);
    CP_COMMIT();

    for (int t = 0; t < T; t++) {
        if (t + 1 < T) { issue(t + 1); CP_COMMIT(); CP_WAIT1(); }
        else           { CP_WAIT0(); }
        __syncthreads();

        uint32_t Ab = smbase + ((t % 3) * 9216 + aoff) * 4;
        uint32_t Bb = smbase + (3 * 9216 + (t % 3) * 4608 + boff) * 4;
        #pragma unroll
        for (int s = 0; s < 4; s++) {     // 4 k16 steps per k64 tile
            uint32_t afr[4][4], bfr[4][2];
            #pragma unroll
            for (int mf = 0; mf < 4; mf++)
                LDSM4(afr[mf][0], afr[mf][1], afr[mf][2], afr[mf][3],
                      Ab + (mf * 576 + 8 * s) * 4);
            LDSM4(bfr[0][0], bfr[0][1], bfr[1][0], bfr[1][1], Bb + 8 * s * 4);
            LDSM4(bfr[2][0], bfr[2][1], bfr[3][0], bfr[3][1], Bb + (16 * 36 + 8 * s) * 4);
            #pragma unroll
            for (int mf = 0; mf < 4; mf++)
                #pragma unroll
                for (int nf = 0; nf < 4; nf++)
                    mma16(acc[mf][nf], afr[mf], bfr[nf]);
        }
        __syncthreads();
    }

    #pragma unroll
    for (int mf = 0; mf < 4; mf++) {
        #pragma unroll
        for (int nf = 0; nf < 4; nf++) {
            int m = m0 + wm + mf * 16 + g;
            int n = n0 + wn + nf * 8 + 2 * t4;
            float2 v0 = make_float2(acc[mf][nf][0], acc[mf][nf][1]);
            float2 v1 = make_float2(acc[mf][nf][2], acc[mf][nf][3]);
            if (EPI >= 1) {
                float2 bz = *reinterpret_cast<const float2*>(bias + n);
                v0.x += bz.x; v0.y += bz.y;
                v1.x += bz.x; v1.y += bz.y;
            }
            if (EPI == 2) {
                float2 r0 = *reinterpret_cast<const float2*>(res + (size_t)m * N + n);
                float2 r1 = *reinterpret_cast<const float2*>(res + (size_t)(m + 8) * N + n);
                v0.x += r0.x; v0.y += r0.y;
                v1.x += r1.x; v1.y += r1.y;
            }
            if (EPI == 3) {
                v0.x = gelu_exact(v0.x); v0.y = gelu_exact(v0.y);
                v1.x = gelu_exact(v1.x); v1.y = gelu_exact(v1.y);
            }
            if (OUTH) {
                uint32_t* Ch = (uint32_t*)Cv;
                Ch[((size_t)m * N + n) >> 1]       = pack2(v0.x, v0.y);
                Ch[((size_t)(m + 8) * N + n) >> 1] = pack2(v1.x, v1.y);
            } else {
                float* Cf = (float*)Cv;
                *reinterpret_cast<float2*>(Cf + (size_t)m * N + n)       = v0;
                *reinterpret_cast<float2*>(Cf + (size_t)(m + 8) * N + n) = v1;
            }
        }
    }
}

// ------------------- host launch -------------------
static void* sym_addr(const void* symbol) {
    void* p = nullptr;
    cudaGetSymbolAddress(&p, symbol);
    return p;
}

extern "C" void kernel_launch(void* const* d_in, const int* in_sizes, int n_in,
                              void* d_out, int out_size) {
    (void)in_sizes; (void)n_in; (void)out_size;
    const float* value = (const float*)d_in[0];
    const float* key   = (const float*)d_in[1];
    const float* query = (const float*)d_in[2];
    const int*   mask  = (const int*)  d_in[3];
    const float* Wv    = (const float*)d_in[4];
    const float* Wk    = (const float*)d_in[5];
    const float* Wq    = (const float*)d_in[6];
    const float* Wo    = (const float*)d_in[7];
    const float* bo    = (const float*)d_in[8];
    const float* ln1_g = (const float*)d_in[9];
    const float* ln1_b = (const float*)d_in[10];
    const float* ln2_g = (const float*)d_in[11];
    const float* ln2_b = (const float*)d_in[12];
    const float* lnf_g = (const float*)d_in[13];
    const float* lnf_b = (const float*)d_in[14];
    const float* W1    = (const float*)d_in[15];
    const float* b1    = (const float*)d_in[16];
    const float* W2    = (const float*)d_in[17];
    const float* b2    = (const float*)d_in[18];
    float* out = (float*)d_out;

    __half*   p_qln_h = (__half*)sym_addr(g_qln_h);
    float*    p_qln   = (float*)sym_addr(g_qln);
    __half*   p_vln_h = (__half*)sym_addr(g_vln_h);
    __half*   p_kln_h = (__half*)sym_addr(g_kln_h);
    __half*   p_Q     = (__half*)sym_addr(g_Q);
    __half*   p_K     = (__half*)sym_addr(g_K);
    __half*   p_V     = (__half*)sym_addr(g_V);
    uint32_t* p_Vp    = (uint32_t*)sym_addr(g_Vp);
    __half*   p_att   = (__half*)sym_addr(g_att);
    float*    p_x     = (float*)sym_addr(g_x);
    __half*   p_hh    = (__half*)sym_addr(g_hh);
    __half*   p_ff    = (__half*)sym_addr(g_ff);
    float*    p_mf    = (float*)sym_addr(g_maskf);
    uint32_t* p_Wq    = (uint32_t*)sym_addr(g_Wq);
    uint32_t* p_Wk    = (uint32_t*)sym_addr(g_Wk);
    uint32_t* p_Wv    = (uint32_t*)sym_addr(g_Wv);
    uint32_t* p_Wo    = (uint32_t*)sym_addr(g_Wo);
    uint32_t* p_W1    = (uint32_t*)sym_addr(g_W1);
    uint32_t* p_W2    = (uint32_t*)sym_addr(g_W2);

    const int GSM = GEMM_SMEM_WORDS * 4;     // 165888
    const int FSM = FLASH_SMEM_WORDS * 4;    // 55296
    cudaFuncSetAttribute(gemm_h<0,1>, cudaFuncAttributeMaxDynamicSharedMemorySize, GSM);
    cudaFuncSetAttribute(gemm_h<2,0>, cudaFuncAttributeMaxDynamicSharedMemorySize, GSM);
    cudaFuncSetAttribute(gemm_h<3,1>, cudaFuncAttributeMaxDynamicSharedMemorySize, GSM);
    cudaFuncSetAttribute(flash_kernel, cudaFuncAttributeMaxDynamicSharedMemorySize, FSM);

    // 0) mask addends + transposed weight packing
    maskf_kernel<<<NTOK / 256, 256>>>(mask, p_mf);
    wpackT_kernel<<<dim3(EDIM/32, EDIM/256), 256>>>(Wq, p_Wq, EDIM, EDIM);
    wpackT_kernel<<<dim3(EDIM/32, EDIM/256), 256>>>(Wk, p_Wk, EDIM, EDIM);
    wpackT_kernel<<<dim3(EDIM/32, EDIM/256), 256>>>(Wv, p_Wv, EDIM, EDIM);
    wpackT_kernel<<<dim3(EDIM/32, EDIM/256), 256>>>(Wo, p_Wo, EDIM, EDIM);
    wpackT_kernel<<<dim3(FFDIM/32, EDIM/256), 256>>>(W1, p_W1, EDIM, FFDIM);
    wpackT_kernel<<<dim3(EDIM/32, FFDIM/256), 256>>>(W2, p_W2, FFDIM, EDIM);

    // 1) pre-norms (half outputs; raw fp32 LN1(q) for residual)
    ln_kernel<<<NTOK/8, 256>>>(query, (uint32_t*)p_qln_h, p_qln, ln1_g, ln1_b);
    ln_kernel<<<NTOK/8, 256>>>(value, (uint32_t*)p_vln_h, nullptr, ln2_g, ln2_b);
    ln_kernel<<<NTOK/8, 256>>>(key,   (uint32_t*)p_kln_h, nullptr, ln2_g, ln2_b);

    // 2) QKV projections (half out)
    dim3 gProj(EDIM / 128, NTOK / 256, 1);
    gemm_h<0,1><<<gProj, 512, GSM>>>(p_qln_h, p_Wq, p_Q, EDIM, EDIM, nullptr, nullptr);
    gemm_h<0,1><<<gProj, 512, GSM>>>(p_kln_h, p_Wk, p_K, EDIM, EDIM, nullptr, nullptr);
    gemm_h<0,1><<<gProj, 512, GSM>>>(p_vln_h, p_Wv, p_V, EDIM, EDIM, nullptr, nullptr);

    // 2b) pack V into token pairs for PV mma B-operand
    vpack_kernel<<<NTOK/2*EDIM/4/256, 256>>>((uint32_t*)p_V, p_Vp);

    // 3) fused attention (half out)
    dim3 gF(SEQ / 128, NHEAD, BATCH);
    flash_kernel<<<gF, 256, FSM>>>(p_Q, p_K, p_Vp, p_mf, (uint32_t*)p_att);

    // 4) x = att @ Wo + bo + LN1(q)_raw  (fp32 out)
    gemm_h<2,0><<<gProj, 512, GSM>>>(p_att, p_Wo, p_x, EDIM, EDIM, bo, p_qln);

    // 5) h = LN_f(x) (half out)
    ln_kernel<<<NTOK/8, 256>>>(p_x, (uint32_t*)p_hh, nullptr, lnf_g, lnf_b);

    // 6) ff = gelu(h @ W1 + b1) (half out)
    dim3 gF1(FFDIM / 128, NTOK / 256, 1);
    gemm_h<3,1><<<gF1, 512, GSM>>>(p_hh, p_W1, p_ff, EDIM, FFDIM, b1, nullptr);

    // 7) out = ff @ W2 + b2 + x (fp32 out)
    dim3 gF2(EDIM / 128, NTOK / 256, 1);
    gemm_h<2,0><<<gF2, 512, GSM>>>(p_ff, p_W2, out, FFDIM, EDIM, b2, p_x);
}

// round 16
// speedup vs baseline: 1.0491x; 1.0491x over previous
#include <cuda_runtime.h>
#include <cuda_fp16.h>
#include <cstdint>
#include <cstddef>

#define EDIM 1024
#define NHEAD 16
#define HDIM 64
#define FFDIM 4096
#define BATCH 4
#define SEQ 2048
#define NTOK (BATCH*SEQ)   // 8192

// ------------------- scratch (device globals; no allocations) -------------------
__device__ __half   g_qln_h[(size_t)NTOK*EDIM];
__device__ float    g_qln  [(size_t)NTOK*EDIM];   // raw fp32 residual
__device__ __half   g_vln_h[(size_t)NTOK*EDIM];
__device__ __half   g_kln_h[(size_t)NTOK*EDIM];
__device__ __half   g_Q [(size_t)NTOK*EDIM];
__device__ __half   g_K [(size_t)NTOK*EDIM];
__device__ __half   g_V [(size_t)NTOK*EDIM];
__device__ uint32_t g_Vp[(size_t)NTOK/2*EDIM];    // token-pair packed V
__device__ __half   g_att[(size_t)NTOK*EDIM];
__device__ float    g_x [(size_t)NTOK*EDIM];
__device__ __half   g_hh[(size_t)NTOK*EDIM];
__device__ __half   g_ff[(size_t)NTOK*FFDIM];
__device__ float    g_maskf[(size_t)BATCH*SEQ];
// weights packed TRANSPOSED: [N][K/2] half2-k-pair words
__device__ uint32_t g_Wq[(size_t)EDIM*EDIM/2];
__device__ uint32_t g_Wk[(size_t)EDIM*EDIM/2];
__device__ uint32_t g_Wv[(size_t)EDIM*EDIM/2];
__device__ uint32_t g_Wo[(size_t)EDIM*EDIM/2];
__device__ uint32_t g_W1[(size_t)FFDIM*EDIM/2];   // [4096][512]
__device__ uint32_t g_W2[(size_t)EDIM*FFDIM/2];   // [1024][2048]

// ------------------- helpers -------------------
__device__ __forceinline__ uint32_t pack2(float lo, float hi) {
    __half2 h = __floats2half2_rn(lo, hi);
    return *reinterpret_cast<uint32_t*>(&h);
}

__device__ __forceinline__ void mma16(float* c, const uint32_t* a, const uint32_t* b) {
    asm volatile(
        "mma.sync.aligned.m16n8k16.row.col.f32.f16.f16.f32 "
        "{%0,%1,%2,%3},{%4,%5,%6,%7},{%8,%9},{%0,%1,%2,%3};\n"
        : "+f"(c[0]), "+f"(c[1]), "+f"(c[2]), "+f"(c[3])
        : "r"(a[0]), "r"(a[1]), "r"(a[2]), "r"(a[3]), "r"(b[0]), "r"(b[1]));
}

#define LDSM4(R0,R1,R2,R3,ADDR) \
    asm volatile("ldmatrix.sync.aligned.m8n8.x4.shared.b16 {%0,%1,%2,%3}, [%4];\n" \
        : "=r"(R0), "=r"(R1), "=r"(R2), "=r"(R3) : "r"(ADDR))

__device__ __forceinline__ float gelu_exact(float v) {
    return 0.5f * v * (1.0f + erff(v * 0.70710678118654752f));
}

#define CP16(dst_sm, src_g) \
    asm volatile("cp.async.cg.shared.global [%0], [%1], 16;\n" :: \
        "r"((uint32_t)__cvta_generic_to_shared(dst_sm)), "l"(src_g))
#define CP_COMMIT() asm volatile("cp.async.commit_group;\n")
#define CP_WAIT1()  asm volatile("cp.async.wait_group 1;\n")
#define CP_WAIT0()  asm volatile("cp.async.wait_group 0;\n")

// ------------------- mask -> float addend -------------------
__global__ __launch_bounds__(256) void maskf_kernel(
    const int* __restrict__ mask, float* __restrict__ mf)
{
    int i = blockIdx.x * 256 + threadIdx.x;
    mf[i] = (mask[i] == 0) ? -1e20f : 0.0f;
}

// ---- weight pack+transpose: fp32 [K][N] -> words [N][K/2] (k-pair minor) ----
__global__ __launch_bounds__(256) void wpackT_kernel(
    const float* __restrict__ W, uint32_t* __restrict__ Wp, int K, int N)
{
    __shared__ float sm[256][33];
    int n0 = blockIdx.x * 32, k0 = blockIdx.y * 256;
    int tid = threadIdx.x;
    #pragma unroll
    for (int i = 0; i < 8; i++) {
        int idx = tid + i * 256;
        int r = idx >> 3, c4 = (idx & 7) * 4;
        float4 v = *reinterpret_cast<const float4*>(W + (size_t)(k0 + r) * N + n0 + c4);
        sm[r][c4] = v.x; sm[r][c4+1] = v.y; sm[r][c4+2] = v.z; sm[r][c4+3] = v.w;
    }
    __syncthreads();
    int Kw = K >> 1;
    #pragma unroll
    for (int i = 0; i < 4; i++) {
        int idx = tid + i * 256;
        int wc = (idx & 7) * 4;
        int n  = (idx >> 3) & 31;
        int kb = idx >> 8;
        int w  = kb * 32 + wc;
        uint4 o;
        o.x = pack2(sm[2*w  ][n], sm[2*w+1][n]);
        o.y = pack2(sm[2*w+2][n], sm[2*w+3][n]);
        o.z = pack2(sm[2*w+4][n], sm[2*w+5][n]);
        o.w = pack2(sm[2*w+6][n], sm[2*w+7][n]);
        *reinterpret_cast<uint4*>(Wp + (size_t)(n0 + n) * Kw + (k0 >> 1) + w) = o;
    }
}

// ------------------- V pack: half [NTOK][E] -> token-pair words [NTOK/2][E] ----
__global__ __launch_bounds__(256) void vpack_kernel(
    const uint32_t* __restrict__ Vh, uint32_t* __restrict__ Vp)
{
    int gid = blockIdx.x * 256 + threadIdx.x;
    int pg = gid >> 8;
    int n = (gid & 255) * 4;
    uint2 a = *reinterpret_cast<const uint2*>(Vh + (size_t)(2 * pg) * 512 + (n >> 1));
    uint2 b = *reinterpret_cast<const uint2*>(Vh + (size_t)(2 * pg + 1) * 512 + (n >> 1));
    uint4 o;
    o.x = (a.x & 0xFFFFu) | (b.x << 16);
    o.y = (a.x >> 16)     | (b.x & 0xFFFF0000u);
    o.z = (a.y & 0xFFFFu) | (b.y << 16);
    o.w = (a.y >> 16)     | (b.y & 0xFFFF0000u);
    *reinterpret_cast<uint4*>(Vp + (size_t)pg * 1024 + n) = o;
}

// ------------------- LayerNorm: warp-per-row -------------------
__global__ __launch_bounds__(256) void ln_kernel(
    const float* __restrict__ in, uint32_t* __restrict__ outh, float* __restrict__ out2,
    const float* __restrict__ gw, const float* __restrict__ gb)
{
    int warp = threadIdx.x >> 5, lane = threadIdx.x & 31;
    int row = blockIdx.x * 8 + warp;
    const float4* inr = reinterpret_cast<const float4*>(in + (size_t)row * EDIM);

    float4 v[8];
    float s = 0.0f, sq = 0.0f;
    #pragma unroll
    for (int i = 0; i < 8; i++) {
        v[i] = inr[lane + 32 * i];
        s  += v[i].x + v[i].y + v[i].z + v[i].w;
        sq += v[i].x*v[i].x + v[i].y*v[i].y + v[i].z*v[i].z + v[i].w*v[i].w;
    }
    #pragma unroll
    for (int o = 16; o > 0; o >>= 1) {
        s  += __shfl_xor_sync(0xffffffffu, s, o);
        sq += __shfl_xor_sync(0xffffffffu, sq, o);
    }
    float mean = s * (1.0f / EDIM);
    float var  = sq * (1.0f / EDIM) - mean * mean;
    float rstd = rsqrtf(var + 1e-5f);

    const float4* gw4 = reinterpret_cast<const float4*>(gw);
    const float4* gb4 = reinterpret_cast<const float4*>(gb);
    #pragma unroll
    for (int i = 0; i < 8; i++) {
        float4 gg = gw4[lane + 32 * i];
        float4 bb = gb4[lane + 32 * i];
        float4 o4;
        o4.x = (v[i].x - mean) * rstd * gg.x + bb.x;
        o4.y = (v[i].y - mean) * rstd * gg.y + bb.y;
        o4.z = (v[i].z - mean) * rstd * gg.z + bb.z;
        o4.w = (v[i].w - mean) * rstd * gg.w + bb.w;
        if (out2)
            reinterpret_cast<float4*>(out2 + (size_t)row * EDIM)[lane + 32 * i] = o4;
        uint2 w2;
        w2.x = pack2(o4.x, o4.y);
        w2.y = pack2(o4.z, o4.w);
        reinterpret_cast<uint2*>(outh + (size_t)row * 512)[lane + 32 * i] = w2;
    }
}

// ------------------- flash attention fp16 + ldmatrix Q/K ---------------------
#define FLASH_SMEM_WORDS 13824

__global__ __launch_bounds__(256, 2) void flash_kernel(
    const __half* __restrict__ Qg, const __half* __restrict__ Kg,
    const uint32_t* __restrict__ Vp, const float* __restrict__ maskf,
    uint32_t* __restrict__ Og)
{
    extern __shared__ uint32_t smu[];
    uint32_t* Qs = smu;
    uint32_t* Ks = smu + 4608;
    uint32_t* Vs = smu + 9216;
    uint32_t smbase = (uint32_t)__cvta_generic_to_shared(smu);

    int qt = blockIdx.x, h = blockIdx.y, b = blockIdx.z;
    int tokbase = b * SEQ + qt * 128;
    const uint32_t* Qw  = (const uint32_t*)Qg + (size_t)tokbase * 512 + h * 32;
    const __half*   Kb0 = Kg + (size_t)b * SEQ * EDIM + h * HDIM;
    const uint32_t* Vp0 = Vp + (size_t)(b * SEQ / 2) * EDIM + h * HDIM;
    const float*    mfb = maskf + (size_t)b * SEQ;

    int tid = threadIdx.x, w = tid >> 5, lane = tid & 31;
    int g = lane >> 2, t4 = lane & 3;
    int r0 = w * 16 + g;

    uint32_t ml = lane >> 3, rl = lane & 7;
    uint32_t qoff = (w * 16 + (ml & 1) * 8 + rl) * 36 + (ml >> 1) * 4;
    uint32_t koff = ((ml >> 1) * 8 + rl) * 36 + (ml & 1) * 4;

    __half2 sc = __float2half2_rn(0.125f);
    #pragma unroll
    for (int it = 0; it < 8; it++) {
        int idx = tid + it * 256;
        int r = idx >> 4, c = (idx & 15) * 2;
        uint2 v = *reinterpret_cast<const uint2*>(Qw + (size_t)r * 512 + c);
        __half2 h0 = __hmul2(*reinterpret_cast<__half2*>(&v.x), sc);
        __half2 h1 = __hmul2(*reinterpret_cast<__half2*>(&v.y), sc);
        uint2 o;
        o.x = *reinterpret_cast<uint32_t*>(&h0);
        o.y = *reinterpret_cast<uint32_t*>(&h1);
        *reinterpret_cast<uint2*>(&Qs[r * 36 + c]) = o;
    }

    auto issue_kv = [&](int j, int buf) {
        const __half* Kc = Kb0 + (size_t)j * 64 * EDIM;
        const uint32_t* Vc = Vp0 + (size_t)(j * 32) * EDIM;
        uint32_t* Kd = Ks + buf * 2304;
        uint32_t* Vd = Vs + buf * 2304;
        #pragma unroll
        for (int it = 0; it < 2; it++) {
            int idx = tid + it * 256;
            int r = idx >> 3, c = idx & 7;
            CP16(&Kd[r * 36 + c * 4], Kc + (size_t)r * EDIM + c * 8);
        }
        #pragma unroll
        for (int it = 0; it < 2; it++) {
            int idx = tid + it * 256;
            int p = idx >> 4, c = idx & 15;
            CP16(&Vd[p * 72 + c * 4], Vc + (size_t)p * EDIM + c * 4);
        }
    };

    issue_kv(0, 0);
    CP_COMMIT();

    float m0 = -1e30f, m1 = -1e30f, l0 = 0.0f, l1 = 0.0f;
    float oacc[8][4];
    #pragma unroll
    for (int nf = 0; nf < 8; nf++)
        #pragma unroll
        for (int i = 0; i < 4; i++) oacc[nf][i] = 0.0f;

    const int NCH = SEQ / 64;
    for (int j = 0; j < NCH; j++) {
        int buf = j & 1;
        if (j + 1 < NCH) { issue_kv(j + 1, buf ^ 1); CP_COMMIT(); CP_WAIT1(); }
        else             { CP_WAIT0(); }
        __syncthreads();

        const uint32_t* Vb = Vs + buf * 2304;
        uint32_t Qb = smbase + qoff * 4;
        uint32_t Kb = smbase + (4608 + buf * 2304 + koff) * 4;

        float sacc[8][4];
        #pragma unroll
        for (int nf = 0; nf < 8; nf++)
            #pragma unroll
            for (int i = 0; i < 4; i++) sacc[nf][i] = 0.0f;

        #pragma unroll
        for (int s = 0; s < 4; s++) {
            uint32_t afr[4];
            LDSM4(afr[0], afr[1], afr[2], afr[3], Qb + 8 * s * 4);
            uint32_t bfr[8][2];
            #pragma unroll
            for (int nf2 = 0; nf2 < 4; nf2++) {
                LDSM4(bfr[2*nf2][0], bfr[2*nf2][1], bfr[2*nf2+1][0], bfr[2*nf2+1][1],
                      Kb + (nf2 * 576 + 8 * s) * 4);
            }
            #pragma unroll
            for (int nf = 0; nf < 8; nf++)
                mma16(sacc[nf], afr, bfr[nf]);
        }

        const float2* mf2 = (const float2*)(mfb + j * 64);
        float mx0 = -1e30f, mx1 = -1e30f;
        #pragma unroll
        for (int nf = 0; nf < 8; nf++) {
            float2 md = mf2[nf * 4 + t4];
            sacc[nf][0] += md.x; sacc[nf][1] += md.y;
            sacc[nf][2] += md.x; sacc[nf][3] += md.y;
            mx0 = fmaxf(mx0, fmaxf(sacc[nf][0], sacc[nf][1]));
            mx1 = fmaxf(mx1, fmaxf(sacc[nf][2], sacc[nf][3]));
        }
        mx0 = fmaxf(mx0, __shfl_xor_sync(0xffffffffu, mx0, 1));
        mx0 = fmaxf(mx0, __shfl_xor_sync(0xffffffffu, mx0, 2));
        mx1 = fmaxf(mx1, __shfl_xor_sync(0xffffffffu, mx1, 1));
        mx1 = fmaxf(mx1, __shfl_xor_sync(0xffffffffu, mx1, 2));
        float mn0 = fmaxf(m0, mx0), mn1 = fmaxf(m1, mx1);
        float c0 = __expf(m0 - mn0), c1 = __expf(m1 - mn1);
        float s0 = 0.0f, s1 = 0.0f;
        uint32_t ppk0[8], ppk1[8];
        #pragma unroll
        for (int nf = 0; nf < 8; nf++) {
            float p00 = __expf(sacc[nf][0] - mn0);
            float p01 = __expf(sacc[nf][1] - mn0);
            float p10 = __expf(sacc[nf][2] - mn1);
            float p11 = __expf(sacc[nf][3] - mn1);
            s0 += p00 + p01; s1 += p10 + p11;
            ppk0[nf] = pack2(p00, p01);
            ppk1[nf] = pack2(p10, p11);
        }
        s0 += __shfl_xor_sync(0xffffffffu, s0, 1);
        s0 += __shfl_xor_sync(0xffffffffu, s0, 2);
        s1 += __shfl_xor_sync(0xffffffffu, s1, 1);
        s1 += __shfl_xor_sync(0xffffffffu, s1, 2);
        l0 = l0 * c0 + s0; l1 = l1 * c1 + s1;
        m0 = mn0; m1 = mn1;

        #pragma unroll
        for (int nf = 0; nf < 8; nf++) {
            oacc[nf][0] *= c0; oacc[nf][1] *= c0;
            oacc[nf][2] *= c1; oacc[nf][3] *= c1;
        }
        #pragma unroll
        for (int s = 0; s < 4; s++) {
            uint32_t afr[4];
            afr[0] = ppk0[2 * s];
            afr[1] = ppk1[2 * s];
            afr[2] = ppk0[2 * s + 1];
            afr[3] = ppk1[2 * s + 1];
            uint32_t bfr[8][2];
            #pragma unroll
            for (int nf = 0; nf < 8; nf++) {
                int n = nf * 8 + g;
                bfr[nf][0] = Vb[(8 * s + t4) * 72 + n];
                bfr[nf][1] = Vb[(8 * s + 4 + t4) * 72 + n];
            }
            #pragma unroll
            for (int nf = 0; nf < 8; nf++)
                mma16(oacc[nf], afr, bfr[nf]);
        }
        __syncthreads();
    }

    float inv0 = 1.0f / l0, inv1 = 1.0f / l1;
    uint32_t* Ob = Og + (size_t)tokbase * 512 + h * 32;
    #pragma unroll
    for (int nf = 0; nf < 8; nf++) {
        int cw = nf * 4 + t4;
        Ob[(size_t)r0 * 512 + cw]       = pack2(oacc[nf][0] * inv0, oacc[nf][1] * inv0);
        Ob[(size_t)(r0 + 8) * 512 + cw] = pack2(oacc[nf][2] * inv1, oacc[nf][3] * inv1);
    }
}

// ---- fp16 NN GEMM, ldmatrix both operands: CTA 128x128, warp 64x32, BK=64 ----
// 3-stage ring, prefetch distance 2. A: half [M][K]; Bp: [N][K/2] words.
#define GEMM_SMEM_WORDS (6*4608)

template<int EPI, int OUTH>
__global__ __launch_bounds__(256, 2) void gemm_h(
    const __half* __restrict__ A, const uint32_t* __restrict__ Bp, void* __restrict__ Cv,
    int K, int N, const float* __restrict__ bias, const float* __restrict__ res)
{
    extern __shared__ uint32_t smu[];
    uint32_t* As = smu;              // 3 x 128 x 36
    uint32_t* Bs = smu + 3 * 4608;   // 3 x 128 x 36 (rows = n)
    uint32_t smbase = (uint32_t)__cvta_generic_to_shared(smu);

    int m0 = blockIdx.y * 128, n0 = blockIdx.x * 128;
    int tid = threadIdx.x, warp = tid >> 5, lane = tid & 31;
    int wm = (warp >> 2) * 64, wn = (warp & 3) * 32;
    int g = lane >> 2, t4 = lane & 3;

    uint32_t ml = lane >> 3, rl = lane & 7;
    uint32_t aoff = (wm + (ml & 1) * 8 + rl) * 36 + (ml >> 1) * 4;
    uint32_t boff = (wn + (ml >> 1) * 8 + rl) * 36 + (ml & 1) * 4;

    const int T = K >> 6;
    const int Kw = K >> 1;

    auto issue = [&](int t) {
        int s = t % 3;
        int k0 = t << 6, p0 = t << 5;
        uint32_t* Ad = As + s * 4608;
        uint32_t* Bd = Bs + s * 4608;
        #pragma unroll
        for (int it = 0; it < 4; it++) {
            int idx = tid + it * 256;
            int r = idx >> 3, c = idx & 7;
            CP16(&Ad[r * 36 + c * 4], A + (size_t)(m0 + r) * K + k0 + c * 8);
        }
        #pragma unroll
        for (int it = 0; it < 4; it++) {
            int idx = tid + it * 256;
            int r = idx >> 3, c = idx & 7;
            CP16(&Bd[r * 36 + c * 4], Bp + (size_t)(n0 + r) * Kw + p0 + c * 4);
        }
    };

    float acc[4][4][4];
    #pragma unroll
    for (int a = 0; a < 4; a++)
        #pragma unroll
        for (int c = 0; c < 4; c++)
            #pragma unroll
            for (int i = 0; i < 4; i++) acc[a][c][i] = 0.0f;

    issue(0); CP_COMMIT();
    if (T > 1) { issue(1); CP_COMMIT(); }

    for (int t = 0; t < T; t++) {
        if (t + 1 < T) CP_WAIT1(); else CP_WAIT0();
        __syncthreads();
        if (t + 2 < T) { issue(t + 2); CP_COMMIT(); }

        uint32_t Ab = smbase + ((t % 3) * 4608 + aoff) * 4;
        uint32_t Bb = smbase + ((3 + (t % 3)) * 4608 + boff) * 4;
        #pragma unroll
        for (int s = 0; s < 4; s++) {     // 4 k16 steps per k64 tile
            uint32_t afr[4][4], bfr[4][2];
            #pragma unroll
            for (int mf = 0; mf < 4; mf++)
                LDSM4(afr[mf][0], afr[mf][1], afr[mf][2], afr[mf][3],
                      Ab + (mf * 576 + 8 * s) * 4);
            LDSM4(bfr[0][0], bfr[0][1], bfr[1][0], bfr[1][1], Bb + 8 * s * 4);
            LDSM4(bfr[2][0], bfr[2][1], bfr[3][0], bfr[3][1], Bb + (16 * 36 + 8 * s) * 4);
            #pragma unroll
            for (int mf = 0; mf < 4; mf++)
                #pragma unroll
                for (int nf = 0; nf < 4; nf++)
                    mma16(acc[mf][nf], afr[mf], bfr[nf]);
        }
    }

    #pragma unroll
    for (int mf = 0; mf < 4; mf++) {
        #pragma unroll
        for (int nf = 0; nf < 4; nf++) {
            int m = m0 + wm + mf * 16 + g;
            int n = n0 + wn + nf * 8 + 2 * t4;
            float2 v0 = make_float2(acc[mf][nf][0], acc[mf][nf][1]);
            float2 v1 = make_float2(acc[mf][nf][2], acc[mf][nf][3]);
            if (EPI >= 1) {
                float2 bz = *reinterpret_cast<const float2*>(bias + n);
                v0.x += bz.x; v0.y += bz.y;
                v1.x += bz.x; v1.y += bz.y;
            }
            if (EPI == 2) {
                float2 r0 = *reinterpret_cast<const float2*>(res + (size_t)m * N + n);
                float2 r1 = *reinterpret_cast<const float2*>(res + (size_t)(m + 8) * N + n);
                v0.x += r0.x; v0.y += r0.y;
                v1.x += r1.x; v1.y += r1.y;
            }
            if (EPI == 3) {
                v0.x = gelu_exact(v0.x); v0.y = gelu_exact(v0.y);
                v1.x = gelu_exact(v1.x); v1.y = gelu_exact(v1.y);
            }
            if (OUTH) {
                uint32_t* Ch = (uint32_t*)Cv;
                Ch[((size_t)m * N + n) >> 1]       = pack2(v0.x, v0.y);
                Ch[((size_t)(m + 8) * N + n) >> 1] = pack2(v1.x, v1.y);
            } else {
                float* Cf = (float*)Cv;
                *reinterpret_cast<float2*>(Cf + (size_t)m * N + n)       = v0;
                *reinterpret_cast<float2*>(Cf + (size_t)(m + 8) * N + n) = v1;
            }
        }
    }
}

// ------------------- host launch -------------------
static void* sym_addr(const void* symbol) {
    void* p = nullptr;
    cudaGetSymbolAddress(&p, symbol);
    return p;
}

extern "C" void kernel_launch(void* const* d_in, const int* in_sizes, int n_in,
                              void* d_out, int out_size) {
    (void)in_sizes; (void)n_in; (void)out_size;
    const float* value = (const float*)d_in[0];
    const float* key   = (const float*)d_in[1];
    const float* query = (const float*)d_in[2];
    const int*   mask  = (const int*)  d_in[3];
    const float* Wv    = (const float*)d_in[4];
    const float* Wk    = (const float*)d_in[5];
    const float* Wq    = (const float*)d_in[6];
    const float* Wo    = (const float*)d_in[7];
    const float* bo    = (const float*)d_in[8];
    const float* ln1_g = (const float*)d_in[9];
    const float* ln1_b = (const float*)d_in[10];
    const float* ln2_g = (const float*)d_in[11];
    const float* ln2_b = (const float*)d_in[12];
    const float* lnf_g = (const float*)d_in[13];
    const float* lnf_b = (const float*)d_in[14];
    const float* W1    = (const float*)d_in[15];
    const float* b1    = (const float*)d_in[16];
    const float* W2    = (const float*)d_in[17];
    const float* b2    = (const float*)d_in[18];
    float* out = (float*)d_out;

    __half*   p_qln_h = (__half*)sym_addr(g_qln_h);
    float*    p_qln   = (float*)sym_addr(g_qln);
    __half*   p_vln_h = (__half*)sym_addr(g_vln_h);
    __half*   p_kln_h = (__half*)sym_addr(g_kln_h);
    __half*   p_Q     = (__half*)sym_addr(g_Q);
    __half*   p_K     = (__half*)sym_addr(g_K);
    __half*   p_V     = (__half*)sym_addr(g_V);
    uint32_t* p_Vp    = (uint32_t*)sym_addr(g_Vp);
    __half*   p_att   = (__half*)sym_addr(g_att);
    float*    p_x     = (float*)sym_addr(g_x);
    __half*   p_hh    = (__half*)sym_addr(g_hh);
    __half*   p_ff    = (__half*)sym_addr(g_ff);
    float*    p_mf    = (float*)sym_addr(g_maskf);
    uint32_t* p_Wq    = (uint32_t*)sym_addr(g_Wq);
    uint32_t* p_Wk    = (uint32_t*)sym_addr(g_Wk);
    uint32_t* p_Wv    = (uint32_t*)sym_addr(g_Wv);
    uint32_t* p_Wo    = (uint32_t*)sym_addr(g_Wo);
    uint32_t* p_W1    = (uint32_t*)sym_addr(g_W1);
    uint32_t* p_W2    = (uint32_t*)sym_addr(g_W2);

    const int GSM = GEMM_SMEM_WORDS * 4;     // 110592
    const int FSM = FLASH_SMEM_WORDS * 4;    // 55296
    cudaFuncSetAttribute(gemm_h<0,1>, cudaFuncAttributeMaxDynamicSharedMemorySize, GSM);
    cudaFuncSetAttribute(gemm_h<2,0>, cudaFuncAttributeMaxDynamicSharedMemorySize, GSM);
    cudaFuncSetAttribute(gemm_h<3,1>, cudaFuncAttributeMaxDynamicSharedMemorySize, GSM);
    cudaFuncSetAttribute(flash_kernel, cudaFuncAttributeMaxDynamicSharedMemorySize, FSM);

    // 0) mask addends + transposed weight packing
    maskf_kernel<<<NTOK / 256, 256>>>(mask, p_mf);
    wpackT_kernel<<<dim3(EDIM/32, EDIM/256), 256>>>(Wq, p_Wq, EDIM, EDIM);
    wpackT_kernel<<<dim3(EDIM/32, EDIM/256), 256>>>(Wk, p_Wk, EDIM, EDIM);
    wpackT_kernel<<<dim3(EDIM/32, EDIM/256), 256>>>(Wv, p_Wv, EDIM, EDIM);
    wpackT_kernel<<<dim3(EDIM/32, EDIM/256), 256>>>(Wo, p_Wo, EDIM, EDIM);
    wpackT_kernel<<<dim3(FFDIM/32, EDIM/256), 256>>>(W1, p_W1, EDIM, FFDIM);
    wpackT_kernel<<<dim3(EDIM/32, FFDIM/256), 256>>>(W2, p_W2, FFDIM, EDIM);

    // 1) pre-norms (half outputs; raw fp32 LN1(q) for residual)
    ln_kernel<<<NTOK/8, 256>>>(query, (uint32_t*)p_qln_h, p_qln, ln1_g, ln1_b);
    ln_kernel<<<NTOK/8, 256>>>(value, (uint32_t*)p_vln_h, nullptr, ln2_g, ln2_b);
    ln_kernel<<<NTOK/8, 256>>>(key,   (uint32_t*)p_kln_h, nullptr, ln2_g, ln2_b);

    // 2) QKV projections (half out)
    dim3 gProj(EDIM / 128, NTOK / 128, 1);
    gemm_h<0,1><<<gProj, 256, GSM>>>(p_qln_h, p_Wq, p_Q, EDIM, EDIM, nullptr, nullptr);
    gemm_h<0,1><<<gProj, 256, GSM>>>(p_kln_h, p_Wk, p_K, EDIM, EDIM, nullptr, nullptr);
    gemm_h<0,1><<<gProj, 256, GSM>>>(p_vln_h, p_Wv, p_V, EDIM, EDIM, nullptr, nullptr);

    // 2b) pack V into token pairs for PV mma B-operand
    vpack_kernel<<<NTOK/2*EDIM/4/256, 256>>>((uint32_t*)p_V, p_Vp);

    // 3) fused attention (half out)
    dim3 gF(SEQ / 128, NHEAD, BATCH);
    flash_kernel<<<gF, 256, FSM>>>(p_Q, p_K, p_Vp, p_mf, (uint32_t*)p_att);

    // 4) x = att @ Wo + bo + LN1(q)_raw  (fp32 out)
    gemm_h<2,0><<<gProj, 256, GSM>>>(p_att, p_Wo, p_x, EDIM, EDIM, bo, p_qln);

    // 5) h = LN_f(x) (half out)
    ln_kernel<<<NTOK/8, 256>>>(p_x, (uint32_t*)p_hh, nullptr, lnf_g, lnf_b);

    // 6) ff = gelu(h @ W1 + b1) (half out)
    dim3 gF1(FFDIM / 128, NTOK / 128, 1);
    gemm_h<3,1><<<gF1, 256, GSM>>>(p_hh, p_W1, p_ff, EDIM, FFDIM, b1, nullptr);

    // 7) out = ff @ W2 + b2 + x (fp32 out)
    dim3 gF2(EDIM / 128, NTOK / 128, 1);
    gemm_h<2,0><<<gF2, 256, GSM>>>(p_ff, p_W2, out, FFDIM, EDIM, b2, p_x);
}

// round 17
// speedup vs baseline: 1.1477x; 1.0940x over previous
#include <cuda_runtime.h>
#include <cuda_fp16.h>
#include <cstdint>
#include <cstddef>

#define EDIM 1024
#define NHEAD 16
#define HDIM 64
#define FFDIM 4096
#define BATCH 4
#define SEQ 2048
#define NTOK (BATCH*SEQ)   // 8192

// ------------------- scratch (device globals; no allocations) -------------------
__device__ __half   g_qln_h[(size_t)NTOK*EDIM];
__device__ float    g_qln  [(size_t)NTOK*EDIM];   // raw fp32 residual
__device__ __half   g_vln_h[(size_t)NTOK*EDIM];
__device__ __half   g_kln_h[(size_t)NTOK*EDIM];
__device__ __half   g_Q [(size_t)NTOK*EDIM];
__device__ __half   g_K [(size_t)NTOK*EDIM];
__device__ __half   g_V [(size_t)NTOK*EDIM];
__device__ uint32_t g_Vp[(size_t)NTOK/2*EDIM];    // token-pair packed V
__device__ __half   g_att[(size_t)NTOK*EDIM];
__device__ float    g_x [(size_t)NTOK*EDIM];
__device__ __half   g_hh[(size_t)NTOK*EDIM];
__device__ __half   g_ff[(size_t)NTOK*FFDIM];
__device__ float    g_maskf[(size_t)BATCH*SEQ];
// weights packed TRANSPOSED: [N][K/2] half2-k-pair words
__device__ uint32_t g_Wq[(size_t)EDIM*EDIM/2];
__device__ uint32_t g_Wk[(size_t)EDIM*EDIM/2];
__device__ uint32_t g_Wv[(size_t)EDIM*EDIM/2];
__device__ uint32_t g_Wo[(size_t)EDIM*EDIM/2];
__device__ uint32_t g_W1[(size_t)FFDIM*EDIM/2];   // [4096][512]
__device__ uint32_t g_W2[(size_t)EDIM*FFDIM/2];   // [1024][2048]

// ------------------- helpers -------------------
__device__ __forceinline__ uint32_t pack2(float lo, float hi) {
    __half2 h = __floats2half2_rn(lo, hi);
    return *reinterpret_cast<uint32_t*>(&h);
}

__device__ __forceinline__ void mma16(float* c, const uint32_t* a, const uint32_t* b) {
    asm volatile(
        "mma.sync.aligned.m16n8k16.row.col.f32.f16.f16.f32 "
        "{%0,%1,%2,%3},{%4,%5,%6,%7},{%8,%9},{%0,%1,%2,%3};\n"
        : "+f"(c[0]), "+f"(c[1]), "+f"(c[2]), "+f"(c[3])
        : "r"(a[0]), "r"(a[1]), "r"(a[2]), "r"(a[3]), "r"(b[0]), "r"(b[1]));
}

#define LDSM4(R0,R1,R2,R3,ADDR) \
    asm volatile("ldmatrix.sync.aligned.m8n8.x4.shared.b16 {%0,%1,%2,%3}, [%4];\n" \
        : "=r"(R0), "=r"(R1), "=r"(R2), "=r"(R3) : "r"(ADDR))

__device__ __forceinline__ float gelu_exact(float v) {
    return 0.5f * v * (1.0f + erff(v * 0.70710678118654752f));
}

#define CP16(dst_sm, src_g) \
    asm volatile("cp.async.cg.shared.global [%0], [%1], 16;\n" :: \
        "r"((uint32_t)__cvta_generic_to_shared(dst_sm)), "l"(src_g))
#define CP_COMMIT() asm volatile("cp.async.commit_group;\n")
#define CP_WAIT1()  asm volatile("cp.async.wait_group 1;\n")
#define CP_WAIT0()  asm volatile("cp.async.wait_group 0;\n")

// ------------------- mask -> float addend -------------------
__global__ __launch_bounds__(256) void maskf_kernel(
    const int* __restrict__ mask, float* __restrict__ mf)
{
    int i = blockIdx.x * 256 + threadIdx.x;
    mf[i] = (mask[i] == 0) ? -1e20f : 0.0f;
}

// ---- weight pack+transpose: fp32 [K][N] -> words [N][K/2] (k-pair minor) ----
__global__ __launch_bounds__(256) void wpackT_kernel(
    const float* __restrict__ W, uint32_t* __restrict__ Wp, int K, int N)
{
    __shared__ float sm[256][33];
    int n0 = blockIdx.x * 32, k0 = blockIdx.y * 256;
    int tid = threadIdx.x;
    #pragma unroll
    for (int i = 0; i < 8; i++) {
        int idx = tid + i * 256;
        int r = idx >> 3, c4 = (idx & 7) * 4;
        float4 v = *reinterpret_cast<const float4*>(W + (size_t)(k0 + r) * N + n0 + c4);
        sm[r][c4] = v.x; sm[r][c4+1] = v.y; sm[r][c4+2] = v.z; sm[r][c4+3] = v.w;
    }
    __syncthreads();
    int Kw = K >> 1;
    #pragma unroll
    for (int i = 0; i < 4; i++) {
        int idx = tid + i * 256;
        int wc = (idx & 7) * 4;
        int n  = (idx >> 3) & 31;
        int kb = idx >> 8;
        int w  = kb * 32 + wc;
        uint4 o;
        o.x = pack2(sm[2*w  ][n], sm[2*w+1][n]);
        o.y = pack2(sm[2*w+2][n], sm[2*w+3][n]);
        o.z = pack2(sm[2*w+4][n], sm[2*w+5][n]);
        o.w = pack2(sm[2*w+6][n], sm[2*w+7][n]);
        *reinterpret_cast<uint4*>(Wp + (size_t)(n0 + n) * Kw + (k0 >> 1) + w) = o;
    }
}

// ------------------- V pack: half [NTOK][E] -> token-pair words [NTOK/2][E] ----
__global__ __launch_bounds__(256) void vpack_kernel(
    const uint32_t* __restrict__ Vh, uint32_t* __restrict__ Vp)
{
    int gid = blockIdx.x * 256 + threadIdx.x;
    int pg = gid >> 8;
    int n = (gid & 255) * 4;
    uint2 a = *reinterpret_cast<const uint2*>(Vh + (size_t)(2 * pg) * 512 + (n >> 1));
    uint2 b = *reinterpret_cast<const uint2*>(Vh + (size_t)(2 * pg + 1) * 512 + (n >> 1));
    uint4 o;
    o.x = (a.x & 0xFFFFu) | (b.x << 16);
    o.y = (a.x >> 16)     | (b.x & 0xFFFF0000u);
    o.z = (a.y & 0xFFFFu) | (b.y << 16);
    o.w = (a.y >> 16)     | (b.y & 0xFFFF0000u);
    *reinterpret_cast<uint4*>(Vp + (size_t)pg * 1024 + n) = o;
}

// ------------------- LayerNorm: warp-per-row -------------------
__global__ __launch_bounds__(256) void ln_kernel(
    const float* __restrict__ in, uint32_t* __restrict__ outh, float* __restrict__ out2,
    const float* __restrict__ gw, const float* __restrict__ gb)
{
    int warp = threadIdx.x >> 5, lane = threadIdx.x & 31;
    int row = blockIdx.x * 8 + warp;
    const float4* inr = reinterpret_cast<const float4*>(in + (size_t)row * EDIM);

    float4 v[8];
    float s = 0.0f, sq = 0.0f;
    #pragma unroll
    for (int i = 0; i < 8; i++) {
        v[i] = inr[lane + 32 * i];
        s  += v[i].x + v[i].y + v[i].z + v[i].w;
        sq += v[i].x*v[i].x + v[i].y*v[i].y + v[i].z*v[i].z + v[i].w*v[i].w;
    }
    #pragma unroll
    for (int o = 16; o > 0; o >>= 1) {
        s  += __shfl_xor_sync(0xffffffffu, s, o);
        sq += __shfl_xor_sync(0xffffffffu, sq, o);
    }
    float mean = s * (1.0f / EDIM);
    float var  = sq * (1.0f / EDIM) - mean * mean;
    float rstd = rsqrtf(var + 1e-5f);

    const float4* gw4 = reinterpret_cast<const float4*>(gw);
    const float4* gb4 = reinterpret_cast<const float4*>(gb);
    #pragma unroll
    for (int i = 0; i < 8; i++) {
        float4 gg = gw4[lane + 32 * i];
        float4 bb = gb4[lane + 32 * i];
        float4 o4;
        o4.x = (v[i].x - mean) * rstd * gg.x + bb.x;
        o4.y = (v[i].y - mean) * rstd * gg.y + bb.y;
        o4.z = (v[i].z - mean) * rstd * gg.z + bb.z;
        o4.w = (v[i].w - mean) * rstd * gg.w + bb.w;
        if (out2)
            reinterpret_cast<float4*>(out2 + (size_t)row * EDIM)[lane + 32 * i] = o4;
        uint2 w2;
        w2.x = pack2(o4.x, o4.y);
        w2.y = pack2(o4.z, o4.w);
        reinterpret_cast<uint2*>(outh + (size_t)row * 512)[lane + 32 * i] = w2;
    }
}

// ------------------- flash attention fp16 + ldmatrix Q/K ---------------------
#define FLASH_SMEM_WORDS 13824

__global__ __launch_bounds__(256, 2) void flash_kernel(
    const __half* __restrict__ Qg, const __half* __restrict__ Kg,
    const uint32_t* __restrict__ Vp, const float* __restrict__ maskf,
    uint32_t* __restrict__ Og)
{
    extern __shared__ uint32_t smu[];
    uint32_t* Qs = smu;
    uint32_t* Ks = smu + 4608;
    uint32_t* Vs = smu + 9216;
    uint32_t smbase = (uint32_t)__cvta_generic_to_shared(smu);

    int qt = blockIdx.x, h = blockIdx.y, b = blockIdx.z;
    int tokbase = b * SEQ + qt * 128;
    const uint32_t* Qw  = (const uint32_t*)Qg + (size_t)tokbase * 512 + h * 32;
    const __half*   Kb0 = Kg + (size_t)b * SEQ * EDIM + h * HDIM;
    const uint32_t* Vp0 = Vp + (size_t)(b * SEQ / 2) * EDIM + h * HDIM;
    const float*    mfb = maskf + (size_t)b * SEQ;

    int tid = threadIdx.x, w = tid >> 5, lane = tid & 31;
    int g = lane >> 2, t4 = lane & 3;
    int r0 = w * 16 + g;

    uint32_t ml = lane >> 3, rl = lane & 7;
    uint32_t qoff = (w * 16 + (ml & 1) * 8 + rl) * 36 + (ml >> 1) * 4;
    uint32_t koff = ((ml >> 1) * 8 + rl) * 36 + (ml & 1) * 4;

    __half2 sc = __float2half2_rn(0.125f);
    #pragma unroll
    for (int it = 0; it < 8; it++) {
        int idx = tid + it * 256;
        int r = idx >> 4, c = (idx & 15) * 2;
        uint2 v = *reinterpret_cast<const uint2*>(Qw + (size_t)r * 512 + c);
        __half2 h0 = __hmul2(*reinterpret_cast<__half2*>(&v.x), sc);
        __half2 h1 = __hmul2(*reinterpret_cast<__half2*>(&v.y), sc);
        uint2 o;
        o.x = *reinterpret_cast<uint32_t*>(&h0);
        o.y = *reinterpret_cast<uint32_t*>(&h1);
        *reinterpret_cast<uint2*>(&Qs[r * 36 + c]) = o;
    }

    auto issue_kv = [&](int j, int buf) {
        const __half* Kc = Kb0 + (size_t)j * 64 * EDIM;
        const uint32_t* Vc = Vp0 + (size_t)(j * 32) * EDIM;
        uint32_t* Kd = Ks + buf * 2304;
        uint32_t* Vd = Vs + buf * 2304;
        #pragma unroll
        for (int it = 0; it < 2; it++) {
            int idx = tid + it * 256;
            int r = idx >> 3, c = idx & 7;
            CP16(&Kd[r * 36 + c * 4], Kc + (size_t)r * EDIM + c * 8);
        }
        #pragma unroll
        for (int it = 0; it < 2; it++) {
            int idx = tid + it * 256;
            int p = idx >> 4, c = idx & 15;
            CP16(&Vd[p * 72 + c * 4], Vc + (size_t)p * EDIM + c * 4);
        }
    };

    issue_kv(0, 0);
    CP_COMMIT();

    float m0 = -1e30f, m1 = -1e30f, l0 = 0.0f, l1 = 0.0f;
    float oacc[8][4];
    #pragma unroll
    for (int nf = 0; nf < 8; nf++)
        #pragma unroll
        for (int i = 0; i < 4; i++) oacc[nf][i] = 0.0f;

    const int NCH = SEQ / 64;
    for (int j = 0; j < NCH; j++) {
        int buf = j & 1;
        if (j + 1 < NCH) { issue_kv(j + 1, buf ^ 1); CP_COMMIT(); CP_WAIT1(); }
        else             { CP_WAIT0(); }
        __syncthreads();

        const uint32_t* Vb = Vs + buf * 2304;
        uint32_t Qb = smbase + qoff * 4;
        uint32_t Kb = smbase + (4608 + buf * 2304 + koff) * 4;

        float sacc[8][4];
        #pragma unroll
        for (int nf = 0; nf < 8; nf++)
            #pragma unroll
            for (int i = 0; i < 4; i++) sacc[nf][i] = 0.0f;

        #pragma unroll
        for (int s = 0; s < 4; s++) {
            uint32_t afr[4];
            LDSM4(afr[0], afr[1], afr[2], afr[3], Qb + 8 * s * 4);
            uint32_t bfr[8][2];
            #pragma unroll
            for (int nf2 = 0; nf2 < 4; nf2++) {
                LDSM4(bfr[2*nf2][0], bfr[2*nf2][1], bfr[2*nf2+1][0], bfr[2*nf2+1][1],
                      Kb + (nf2 * 576 + 8 * s) * 4);
            }
            #pragma unroll
            for (int nf = 0; nf < 8; nf++)
                mma16(sacc[nf], afr, bfr[nf]);
        }

        const float2* mf2 = (const float2*)(mfb + j * 64);
        float mx0 = -1e30f, mx1 = -1e30f;
        #pragma unroll
        for (int nf = 0; nf < 8; nf++) {
            float2 md = mf2[nf * 4 + t4];
            sacc[nf][0] += md.x; sacc[nf][1] += md.y;
            sacc[nf][2] += md.x; sacc[nf][3] += md.y;
            mx0 = fmaxf(mx0, fmaxf(sacc[nf][0], sacc[nf][1]));
            mx1 = fmaxf(mx1, fmaxf(sacc[nf][2], sacc[nf][3]));
        }
        mx0 = fmaxf(mx0, __shfl_xor_sync(0xffffffffu, mx0, 1));
        mx0 = fmaxf(mx0, __shfl_xor_sync(0xffffffffu, mx0, 2));
        mx1 = fmaxf(mx1, __shfl_xor_sync(0xffffffffu, mx1, 1));
        mx1 = fmaxf(mx1, __shfl_xor_sync(0xffffffffu, mx1, 2));
        float mn0 = fmaxf(m0, mx0), mn1 = fmaxf(m1, mx1);
        float c0 = __expf(m0 - mn0), c1 = __expf(m1 - mn1);
        float s0 = 0.0f, s1 = 0.0f;
        uint32_t ppk0[8], ppk1[8];
        #pragma unroll
        for (int nf = 0; nf < 8; nf++) {
            float p00 = __expf(sacc[nf][0] - mn0);
            float p01 = __expf(sacc[nf][1] - mn0);
            float p10 = __expf(sacc[nf][2] - mn1);
            float p11 = __expf(sacc[nf][3] - mn1);
            s0 += p00 + p01; s1 += p10 + p11;
            ppk0[nf] = pack2(p00, p01);
            ppk1[nf] = pack2(p10, p11);
        }
        s0 += __shfl_xor_sync(0xffffffffu, s0, 1);
        s0 += __shfl_xor_sync(0xffffffffu, s0, 2);
        s1 += __shfl_xor_sync(0xffffffffu, s1, 1);
        s1 += __shfl_xor_sync(0xffffffffu, s1, 2);
        l0 = l0 * c0 + s0; l1 = l1 * c1 + s1;
        m0 = mn0; m1 = mn1;

        #pragma unroll
        for (int nf = 0; nf < 8; nf++) {
            oacc[nf][0] *= c0; oacc[nf][1] *= c0;
            oacc[nf][2] *= c1; oacc[nf][3] *= c1;
        }
        #pragma unroll
        for (int s = 0; s < 4; s++) {
            uint32_t afr[4];
            afr[0] = ppk0[2 * s];
            afr[1] = ppk1[2 * s];
            afr[2] = ppk0[2 * s + 1];
            afr[3] = ppk1[2 * s + 1];
            uint32_t bfr[8][2];
            #pragma unroll
            for (int nf = 0; nf < 8; nf++) {
                int n = nf * 8 + g;
                bfr[nf][0] = Vb[(8 * s + t4) * 72 + n];
                bfr[nf][1] = Vb[(8 * s + 4 + t4) * 72 + n];
            }
            #pragma unroll
            for (int nf = 0; nf < 8; nf++)
                mma16(oacc[nf], afr, bfr[nf]);
        }
        __syncthreads();
    }

    float inv0 = 1.0f / l0, inv1 = 1.0f / l1;
    uint32_t* Ob = Og + (size_t)tokbase * 512 + h * 32;
    #pragma unroll
    for (int nf = 0; nf < 8; nf++) {
        int cw = nf * 4 + t4;
        Ob[(size_t)r0 * 512 + cw]       = pack2(oacc[nf][0] * inv0, oacc[nf][1] * inv0);
        Ob[(size_t)(r0 + 8) * 512 + cw] = pack2(oacc[nf][2] * inv1, oacc[nf][3] * inv1);
    }
}

// ---- fp16 NN GEMM core (R12 schedule), shared by single and batched kernels ----
#define GEMM_SMEM_WORDS (6*4608)

template<int EPI, int OUTH>
__device__ __forceinline__ void gemm_body(
    const __half* __restrict__ A, const uint32_t* __restrict__ Bp, void* __restrict__ Cv,
    int K, int N, const float* __restrict__ bias, const float* __restrict__ res,
    int m0, int n0)
{
    extern __shared__ uint32_t smu[];
    uint32_t* As = smu;              // 3 x 128 x 36
    uint32_t* Bs = smu + 3 * 4608;   // 3 x 128 x 36 (rows = n)
    uint32_t smbase = (uint32_t)__cvta_generic_to_shared(smu);

    int tid = threadIdx.x, warp = tid >> 5, lane = tid & 31;
    int wm = (warp >> 2) * 64, wn = (warp & 3) * 32;
    int g = lane >> 2, t4 = lane & 3;

    uint32_t ml = lane >> 3, rl = lane & 7;
    uint32_t aoff = (wm + (ml & 1) * 8 + rl) * 36 + (ml >> 1) * 4;
    uint32_t boff = (wn + (ml >> 1) * 8 + rl) * 36 + (ml & 1) * 4;

    const int T = K >> 6;
    const int Kw = K >> 1;

    auto issue = [&](int t) {
        int s = t % 3;
        int k0 = t << 6, p0 = t << 5;
        uint32_t* Ad = As + s * 4608;
        uint32_t* Bd = Bs + s * 4608;
        #pragma unroll
        for (int it = 0; it < 4; it++) {
            int idx = tid + it * 256;
            int r = idx >> 3, c = idx & 7;
            CP16(&Ad[r * 36 + c * 4], A + (size_t)(m0 + r) * K + k0 + c * 8);
        }
        #pragma unroll
        for (int it = 0; it < 4; it++) {
            int idx = tid + it * 256;
            int r = idx >> 3, c = idx & 7;
            CP16(&Bd[r * 36 + c * 4], Bp + (size_t)(n0 + r) * Kw + p0 + c * 4);
        }
    };

    float acc[4][4][4];
    #pragma unroll
    for (int a = 0; a < 4; a++)
        #pragma unroll
        for (int c = 0; c < 4; c++)
            #pragma unroll
            for (int i = 0; i < 4; i++) acc[a][c][i] = 0.0f;

    issue(0);
    CP_COMMIT();

    for (int t = 0; t < T; t++) {
        if (t + 1 < T) { issue(t + 1); CP_COMMIT(); CP_WAIT1(); }
        else           { CP_WAIT0(); }
        __syncthreads();

        uint32_t Ab = smbase + ((t % 3) * 4608 + aoff) * 4;
        uint32_t Bb = smbase + ((3 + (t % 3)) * 4608 + boff) * 4;
        #pragma unroll
        for (int s = 0; s < 4; s++) {
            uint32_t afr[4][4], bfr[4][2];
            #pragma unroll
            for (int mf = 0; mf < 4; mf++)
                LDSM4(afr[mf][0], afr[mf][1], afr[mf][2], afr[mf][3],
                      Ab + (mf * 576 + 8 * s) * 4);
            LDSM4(bfr[0][0], bfr[0][1], bfr[1][0], bfr[1][1], Bb + 8 * s * 4);
            LDSM4(bfr[2][0], bfr[2][1], bfr[3][0], bfr[3][1], Bb + (16 * 36 + 8 * s) * 4);
            #pragma unroll
            for (int mf = 0; mf < 4; mf++)
                #pragma unroll
                for (int nf = 0; nf < 4; nf++)
                    mma16(acc[mf][nf], afr[mf], bfr[nf]);
        }
    }

    #pragma unroll
    for (int mf = 0; mf < 4; mf++) {
        #pragma unroll
        for (int nf = 0; nf < 4; nf++) {
            int m = m0 + wm + mf * 16 + g;
            int n = n0 + wn + nf * 8 + 2 * t4;
            float2 v0 = make_float2(acc[mf][nf][0], acc[mf][nf][1]);
            float2 v1 = make_float2(acc[mf][nf][2], acc[mf][nf][3]);
            if (EPI >= 1) {
                float2 bz = *reinterpret_cast<const float2*>(bias + n);
                v0.x += bz.x; v0.y += bz.y;
                v1.x += bz.x; v1.y += bz.y;
            }
            if (EPI == 2) {
                float2 r0 = *reinterpret_cast<const float2*>(res + (size_t)m * N + n);
                float2 r1 = *reinterpret_cast<const float2*>(res + (size_t)(m + 8) * N + n);
                v0.x += r0.x; v0.y += r0.y;
                v1.x += r1.x; v1.y += r1.y;
            }
            if (EPI == 3) {
                v0.x = gelu_exact(v0.x); v0.y = gelu_exact(v0.y);
                v1.x = gelu_exact(v1.x); v1.y = gelu_exact(v1.y);
            }
            if (OUTH) {
                uint32_t* Ch = (uint32_t*)Cv;
                Ch[((size_t)m * N + n) >> 1]       = pack2(v0.x, v0.y);
                Ch[((size_t)(m + 8) * N + n) >> 1] = pack2(v1.x, v1.y);
            } else {
                float* Cf = (float*)Cv;
                *reinterpret_cast<float2*>(Cf + (size_t)m * N + n)       = v0;
                *reinterpret_cast<float2*>(Cf + (size_t)(m + 8) * N + n) = v1;
            }
        }
    }
}

template<int EPI, int OUTH>
__global__ __launch_bounds__(256, 2) void gemm_h(
    const __half* __restrict__ A, const uint32_t* __restrict__ Bp, void* __restrict__ Cv,
    int K, int N, const float* __restrict__ bias, const float* __restrict__ res)
{
    gemm_body<EPI, OUTH>(A, Bp, Cv, K, N, bias, res,
                         blockIdx.y * 128, blockIdx.x * 128);
}

// batched QKV: blockIdx.z selects (A, W, C) triple; one launch, fewer wave tails
__global__ __launch_bounds__(256, 2) void gemm_qkv(
    const __half* A0, const __half* A1, const __half* A2,
    const uint32_t* B0, const uint32_t* B1, const uint32_t* B2,
    void* C0, void* C1, void* C2)
{
    const __half* A = (blockIdx.z == 0) ? A0 : (blockIdx.z == 1) ? A1 : A2;
    const uint32_t* Bp = (blockIdx.z == 0) ? B0 : (blockIdx.z == 1) ? B1 : B2;
    void* Cv = (blockIdx.z == 0) ? C0 : (blockIdx.z == 1) ? C1 : C2;
    gemm_body<0, 1>(A, Bp, Cv, EDIM, EDIM, nullptr, nullptr,
                    blockIdx.y * 128, blockIdx.x * 128);
}

// ------------------- host launch -------------------
static void* sym_addr(const void* symbol) {
    void* p = nullptr;
    cudaGetSymbolAddress(&p, symbol);
    return p;
}

extern "C" void kernel_launch(void* const* d_in, const int* in_sizes, int n_in,
                              void* d_out, int out_size) {
    (void)in_sizes; (void)n_in; (void)out_size;
    const float* value = (const float*)d_in[0];
    const float* key   = (const float*)d_in[1];
    const float* query = (const float*)d_in[2];
    const int*   mask  = (const int*)  d_in[3];
    const float* Wv    = (const float*)d_in[4];
    const float* Wk    = (const float*)d_in[5];
    const float* Wq    = (const float*)d_in[6];
    const float* Wo    = (const float*)d_in[7];
    const float* bo    = (const float*)d_in[8];
    const float* ln1_g = (const float*)d_in[9];
    const float* ln1_b = (const float*)d_in[10];
    const float* ln2_g = (const float*)d_in[11];
    const float* ln2_b = (const float*)d_in[12];
    const float* lnf_g = (const float*)d_in[13];
    const float* lnf_b = (const float*)d_in[14];
    const float* W1    = (const float*)d_in[15];
    const float* b1    = (const float*)d_in[16];
    const float* W2    = (const float*)d_in[17];
    const float* b2    = (const float*)d_in[18];
    float* out = (float*)d_out;

    __half*   p_qln_h = (__half*)sym_addr(g_qln_h);
    float*    p_qln   = (float*)sym_addr(g_qln);
    __half*   p_vln_h = (__half*)sym_addr(g_vln_h);
    __half*   p_kln_h = (__half*)sym_addr(g_kln_h);
    __half*   p_Q     = (__half*)sym_addr(g_Q);
    __half*   p_K     = (__half*)sym_addr(g_K);
    __half*   p_V     = (__half*)sym_addr(g_V);
    uint32_t* p_Vp    = (uint32_t*)sym_addr(g_Vp);
    __half*   p_att   = (__half*)sym_addr(g_att);
    float*    p_x     = (float*)sym_addr(g_x);
    __half*   p_hh    = (__half*)sym_addr(g_hh);
    __half*   p_ff    = (__half*)sym_addr(g_ff);
    float*    p_mf    = (float*)sym_addr(g_maskf);
    uint32_t* p_Wq    = (uint32_t*)sym_addr(g_Wq);
    uint32_t* p_Wk    = (uint32_t*)sym_addr(g_Wk);
    uint32_t* p_Wv    = (uint32_t*)sym_addr(g_Wv);
    uint32_t* p_Wo    = (uint32_t*)sym_addr(g_Wo);
    uint32_t* p_W1    = (uint32_t*)sym_addr(g_W1);
    uint32_t* p_W2    = (uint32_t*)sym_addr(g_W2);

    const int GSM = GEMM_SMEM_WORDS * 4;     // 110592
    const int FSM = FLASH_SMEM_WORDS * 4;    // 55296
    cudaFuncSetAttribute(gemm_h<0,1>, cudaFuncAttributeMaxDynamicSharedMemorySize, GSM);
    cudaFuncSetAttribute(gemm_h<2,0>, cudaFuncAttributeMaxDynamicSharedMemorySize, GSM);
    cudaFuncSetAttribute(gemm_h<3,1>, cudaFuncAttributeMaxDynamicSharedMemorySize, GSM);
    cudaFuncSetAttribute(gemm_qkv, cudaFuncAttributeMaxDynamicSharedMemorySize, GSM);
    cudaFuncSetAttribute(flash_kernel, cudaFuncAttributeMaxDynamicSharedMemorySize, FSM);

    // 0) mask addends + transposed weight packing
    maskf_kernel<<<NTOK / 256, 256>>>(mask, p_mf);
    wpackT_kernel<<<dim3(EDIM/32, EDIM/256), 256>>>(Wq, p_Wq, EDIM, EDIM);
    wpackT_kernel<<<dim3(EDIM/32, EDIM/256), 256>>>(Wk, p_Wk, EDIM, EDIM);
    wpackT_kernel<<<dim3(EDIM/32, EDIM/256), 256>>>(Wv, p_Wv, EDIM, EDIM);
    wpackT_kernel<<<dim3(EDIM/32, EDIM/256), 256>>>(Wo, p_Wo, EDIM, EDIM);
    wpackT_kernel<<<dim3(FFDIM/32, EDIM/256), 256>>>(W1, p_W1, EDIM, FFDIM);
    wpackT_kernel<<<dim3(EDIM/32, FFDIM/256), 256>>>(W2, p_W2, FFDIM, EDIM);

    // 1) pre-norms (half outputs; raw fp32 LN1(q) for residual)
    ln_kernel<<<NTOK/8, 256>>>(query, (uint32_t*)p_qln_h, p_qln, ln1_g, ln1_b);
    ln_kernel<<<NTOK/8, 256>>>(value, (uint32_t*)p_vln_h, nullptr, ln2_g, ln2_b);
    ln_kernel<<<NTOK/8, 256>>>(key,   (uint32_t*)p_kln_h, nullptr, ln2_g, ln2_b);

    // 2) QKV projections, single batched launch (half out)
    dim3 gQKV(EDIM / 128, NTOK / 128, 3);
    gemm_qkv<<<gQKV, 256, GSM>>>(p_qln_h, p_kln_h, p_vln_h,
                                 p_Wq, p_Wk, p_Wv, p_Q, p_K, p_V);

    // 2b) pack V into token pairs for PV mma B-operand
    vpack_kernel<<<NTOK/2*EDIM/4/256, 256>>>((uint32_t*)p_V, p_Vp);

    // 3) fused attention (half out)
    dim3 gF(SEQ / 128, NHEAD, BATCH);
    flash_kernel<<<gF, 256, FSM>>>(p_Q, p_K, p_Vp, p_mf, (uint32_t*)p_att);

    // 4) x = att @ Wo + bo + LN1(q)_raw  (fp32 out)
    dim3 gProj(EDIM / 128, NTOK / 128, 1);
    gemm_h<2,0><<<gProj, 256, GSM>>>(p_att, p_Wo, p_x, EDIM, EDIM, bo, p_qln);

    // 5) h = LN_f(x) (half out)
    ln_kernel<<<NTOK/8, 256>>>(p_x, (uint32_t*)p_hh, nullptr, lnf_g, lnf_b);

    // 6) ff = gelu(h @ W1 + b1) (half out)
    dim3 gF1(FFDIM / 128, NTOK / 128, 1);
    gemm_h<3,1><<<gF1, 256, GSM>>>(p_hh, p_W1, p_ff, EDIM, FFDIM, b1, nullptr);

    // 7) out = ff @ W2 + b2 + x (fp32 out)
    dim3 gF2(EDIM / 128, NTOK / 128, 1);
    gemm_h<2,0><<<gF2, 256, GSM>>>(p_ff, p_W2, out, FFDIM, EDIM, b2, p_x);
}